// round 10
// baseline (speedup 1.0000x reference)
#include <cuda_runtime.h>
#include <cuda_bf16.h>
#include <math.h>
#include <stdint.h>

#define NNODES 50000
#define KNEI   32
#define DIM    128
#define DOUT   128
#define BM     128
#define BK     32

// gemm1 (tf32) smem geometry (u32)
#define A1STR  36
#define B1STR  136
#define B1_OFF (BM * A1STR)             // 4608
#define STG1_U32 (B1_OFF + BK * B1STR)  // 8960
// gemm2 (bf16) smem geometry (u32)
#define A2STR  20
#define B2STR  20
#define B2_OFF (BM * A2STR)             // 2560
#define STG2_U32 (B2_OFF + BM * B2STR)  // 5120
#define NSTAGE 3

// Static device scratch (allowed).
__device__ __nv_bfloat16 g_f1b[(size_t)NNODES * DIM];   // bf16(fea1)
__device__ __nv_bfloat16 g_n1b[(size_t)NNODES * DIM];   // bf16(mean nei1)
__device__ __nv_bfloat16 g_n2b[(size_t)NNODES * DIM];   // bf16(mean nei2)
__device__ uint32_t g_Wt[(size_t)256 * DOUT];           // tf32(W[0:256]), [k][n]
__device__ __nv_bfloat16 g_Wb[(size_t)DOUT * 256];      // bf16(W[256:512]), [n][k']
__device__ float    g_part[(size_t)NNODES * DOUT];      // fp32 partial (f-half)

__device__ __forceinline__ uint32_t f2tf32(float f) {
    uint32_t u;
    asm("cvt.rna.tf32.f32 %0, %1;" : "=r"(u) : "f"(f));
    return u;
}
__device__ __forceinline__ uint32_t smem_u32p(const void* p) {
    uint32_t a;
    asm("{ .reg .u64 t; cvta.to.shared.u64 t, %1; cvt.u32.u64 %0, t; }" : "=r"(a) : "l"(p));
    return a;
}
__device__ __forceinline__ void cp_async16(uint32_t dst, const void* src) {
    asm volatile("cp.async.cg.shared.global [%0], [%1], 16;"
                 :: "r"(dst), "l"(src) : "memory");
}
#define CP_COMMIT() asm volatile("cp.async.commit_group;" ::: "memory")
#define CP_WAIT1()  asm volatile("cp.async.wait_group 1;"  ::: "memory")

__device__ __forceinline__ void mma_tf32(float c[4], const uint32_t a[4],
                                         const uint32_t b[2]) {
    asm volatile(
        "mma.sync.aligned.m16n8k8.row.col.f32.tf32.tf32.f32 "
        "{%0,%1,%2,%3}, {%4,%5,%6,%7}, {%8,%9}, {%0,%1,%2,%3};"
        : "+f"(c[0]), "+f"(c[1]), "+f"(c[2]), "+f"(c[3])
        : "r"(a[0]), "r"(a[1]), "r"(a[2]), "r"(a[3]), "r"(b[0]), "r"(b[1]));
}
__device__ __forceinline__ void mma_bf16(float c[4], const uint32_t a[4],
                                         const uint32_t b[2]) {
    asm volatile(
        "mma.sync.aligned.m16n8k16.row.col.f32.bf16.bf16.f32 "
        "{%0,%1,%2,%3}, {%4,%5,%6,%7}, {%8,%9}, {%0,%1,%2,%3};"
        : "+f"(c[0]), "+f"(c[1]), "+f"(c[2]), "+f"(c[3])
        : "r"(a[0]), "r"(a[1]), "r"(a[2]), "r"(a[3]), "r"(b[0]), "r"(b[1]));
}

// ---------------------------------------------------------------------------
// conv: fea1 -> bf16 ; W[0:256] -> tf32 [k][n] ; W[256:512] -> bf16 [n][k']
// ---------------------------------------------------------------------------
__global__ __launch_bounds__(256)
void conv_kernel(const float* __restrict__ fea1, const float* __restrict__ W) {
    const int t = blockIdx.x * 256 + threadIdx.x;   // 0..799999
    {
        float4 a = reinterpret_cast<const float4*>(fea1)[2 * (size_t)t];
        float4 b = reinterpret_cast<const float4*>(fea1)[2 * (size_t)t + 1];
        __nv_bfloat162 p0 = __floats2bfloat162_rn(a.x, a.y);
        __nv_bfloat162 p1 = __floats2bfloat162_rn(a.z, a.w);
        __nv_bfloat162 p2 = __floats2bfloat162_rn(b.x, b.y);
        __nv_bfloat162 p3 = __floats2bfloat162_rn(b.z, b.w);
        uint4 o;
        o.x = *reinterpret_cast<uint32_t*>(&p0);
        o.y = *reinterpret_cast<uint32_t*>(&p1);
        o.z = *reinterpret_cast<uint32_t*>(&p2);
        o.w = *reinterpret_cast<uint32_t*>(&p3);
        reinterpret_cast<uint4*>(g_f1b)[t] = o;
    }
    if (t < (256 * DOUT) / 4) {
        float4 w = reinterpret_cast<const float4*>(W)[t];
        uint4 o;
        o.x = f2tf32(w.x); o.y = f2tf32(w.y); o.z = f2tf32(w.z); o.w = f2tf32(w.w);
        reinterpret_cast<uint4*>(g_Wt)[t] = o;
    }
    if (t < DOUT * 128) {
        int n  = t >> 7;
        int kp = t & 127;
        float w0 = W[(size_t)(256 + 2 * kp) * DOUT + n];
        float w1 = W[(size_t)(257 + 2 * kp) * DOUT + n];
        __nv_bfloat162 p = __floats2bfloat162_rn(w0, w1);
        reinterpret_cast<uint32_t*>(g_Wb)[n * 128 + kp] =
            *reinterpret_cast<uint32_t*>(&p);
    }
}

// ---------------------------------------------------------------------------
// agg: one warp per node; bf16 gather, fp32 accum, bf16 means.
// ---------------------------------------------------------------------------
__global__ __launch_bounds__(256)
void agg_kernel(const int* __restrict__ idx1, const int* __restrict__ idx2) {
    const int node = blockIdx.x * 8 + (threadIdx.x >> 5);
    const int lane = threadIdx.x & 31;
    const uint2* fb = reinterpret_cast<const uint2*>(g_f1b);
    const float sc = 1.0f / (float)KNEI;

    #pragma unroll
    for (int list = 0; list < 2; list++) {
        const int* idx = list ? idx2 : idx1;
        __nv_bfloat16* dst = list ? g_n2b : g_n1b;
        int myidx = idx[node * KNEI + lane];
        float4 a0 = make_float4(0.f, 0.f, 0.f, 0.f);
        float4 a1 = make_float4(0.f, 0.f, 0.f, 0.f);
        #pragma unroll
        for (int j = 0; j < KNEI; j += 2) {
            int i0 = __shfl_sync(0xffffffffu, myidx, j + 0);
            int i1 = __shfl_sync(0xffffffffu, myidx, j + 1);
            uint2 v0 = __ldg(&fb[(size_t)i0 * 32 + lane]);
            uint2 v1 = __ldg(&fb[(size_t)i1 * 32 + lane]);
            float2 l0 = __bfloat1622float2(*reinterpret_cast<__nv_bfloat162*>(&v0.x));
            float2 h0 = __bfloat1622float2(*reinterpret_cast<__nv_bfloat162*>(&v0.y));
            float2 l1 = __bfloat1622float2(*reinterpret_cast<__nv_bfloat162*>(&v1.x));
            float2 h1 = __bfloat1622float2(*reinterpret_cast<__nv_bfloat162*>(&v1.y));
            a0.x += l0.x; a0.y += l0.y; a0.z += h0.x; a0.w += h0.y;
            a1.x += l1.x; a1.y += l1.y; a1.z += h1.x; a1.w += h1.y;
        }
        __nv_bfloat162 m0 = __floats2bfloat162_rn((a0.x + a1.x) * sc, (a0.y + a1.y) * sc);
        __nv_bfloat162 m1 = __floats2bfloat162_rn((a0.z + a1.z) * sc, (a0.w + a1.w) * sc);
        uint2 o;
        o.x = *reinterpret_cast<uint32_t*>(&m0);
        o.y = *reinterpret_cast<uint32_t*>(&m1);
        *reinterpret_cast<uint2*>(&dst[(size_t)node * DIM + lane * 4]) = o;
    }
}

// ---------------------------------------------------------------------------
// gemm1: g_part = [f1|f2] @ W[0:256]  (tf32, 3-stage pipeline, 8 chunks)
// ---------------------------------------------------------------------------
__global__ __launch_bounds__(256, 2)
void gemm1_kernel(const float* __restrict__ fea1,
                  const float* __restrict__ fea2) {
    extern __shared__ uint32_t smem[];
    const int tid  = threadIdx.x;
    const int wid  = tid >> 5;
    const int lane = tid & 31;
    const int gid  = lane >> 2;
    const int tig  = lane & 3;
    const int warp_m = (wid >> 2) * 64;
    const int warp_n = (wid & 3) * 32;
    const int block_row = blockIdx.x * BM;
    const uint32_t sbase = smem_u32p(smem);

    auto load_chunk = [&](int kc, int stage) {
        const uint32_t aB = sbase + stage * (STG1_U32 * 4);
        const uint32_t bB = aB + B1_OFF * 4;
        const float* F = (kc < 4) ? fea1 : fea2;
        const int colb = (kc & 3) * BK;
        #pragma unroll
        for (int i = 0; i < 4; i++) {
            int u  = tid + i * 256;
            int r  = u >> 3;
            int c4 = u & 7;
            int gr = block_row + r;
            if (gr >= NNODES) gr = NNODES - 1;
            cp_async16(aB + r * (A1STR * 4) + c4 * 16,
                       F + (size_t)gr * DIM + colb + c4 * 4);
        }
        #pragma unroll
        for (int i = 0; i < 4; i++) {
            int u  = tid + i * 256;
            int k  = u >> 5;
            int n4 = u & 31;
            cp_async16(bB + k * (B1STR * 4) + n4 * 16,
                       g_Wt + (size_t)(kc * BK + k) * DOUT + n4 * 4);
        }
    };

    float acc[4][4][4];
    #pragma unroll
    for (int mt = 0; mt < 4; mt++)
        #pragma unroll
        for (int nt = 0; nt < 4; nt++)
            #pragma unroll
            for (int i = 0; i < 4; i++)
                acc[mt][nt][i] = 0.f;

    load_chunk(0, 0); CP_COMMIT();
    load_chunk(1, 1); CP_COMMIT();

    #pragma unroll 1
    for (int kc = 0; kc < 8; kc++) {
        CP_WAIT1();
        __syncthreads();
        if (kc + 2 < 8) load_chunk(kc + 2, (kc + 2) % NSTAGE);
        CP_COMMIT();

        const uint32_t* sA = smem + (kc % NSTAGE) * STG1_U32;
        const uint32_t* sB = sA + B1_OFF;
        #pragma unroll
        for (int ks = 0; ks < 4; ks++) {
            const int ko = ks * 8;
            uint32_t af[4][4];
            #pragma unroll
            for (int mt = 0; mt < 4; mt++) {
                int row = warp_m + mt * 16 + gid;
                af[mt][0] = f2tf32(__uint_as_float(sA[row * A1STR + ko + tig]));
                af[mt][1] = f2tf32(__uint_as_float(sA[(row + 8) * A1STR + ko + tig]));
                af[mt][2] = f2tf32(__uint_as_float(sA[row * A1STR + ko + tig + 4]));
                af[mt][3] = f2tf32(__uint_as_float(sA[(row + 8) * A1STR + ko + tig + 4]));
            }
            uint32_t bf[4][2];
            #pragma unroll
            for (int nt = 0; nt < 4; nt++) {
                int col = warp_n + nt * 8 + gid;
                bf[nt][0] = sB[(ko + tig) * B1STR + col];
                bf[nt][1] = sB[(ko + tig + 4) * B1STR + col];
            }
            #pragma unroll
            for (int mt = 0; mt < 4; mt++)
                #pragma unroll
                for (int nt = 0; nt < 4; nt++)
                    mma_tf32(acc[mt][nt], af[mt], bf[nt]);
        }
        __syncthreads();
    }

    #pragma unroll
    for (int mt = 0; mt < 4; mt++) {
        #pragma unroll
        for (int half = 0; half < 2; half++) {
            int gr = block_row + warp_m + mt * 16 + gid + half * 8;
            if (gr < NNODES) {
                #pragma unroll
                for (int nt = 0; nt < 4; nt++) {
                    float2 v;
                    v.x = acc[mt][nt][half * 2 + 0];
                    v.y = acc[mt][nt][half * 2 + 1];
                    *reinterpret_cast<float2*>(
                        g_part + (size_t)gr * DOUT + warp_n + nt * 8 + tig * 2) = v;
                }
            }
        }
    }
}

// ---------------------------------------------------------------------------
// gemm2: out = tanh(g_part + [n1|n2] @ W[256:512])  (bf16 mma, 8 chunks)
// ---------------------------------------------------------------------------
__global__ __launch_bounds__(256, 2)
void gemm2_kernel(float* __restrict__ out) {
    extern __shared__ uint32_t smem[];
    const int tid  = threadIdx.x;
    const int wid  = tid >> 5;
    const int lane = tid & 31;
    const int gid  = lane >> 2;
    const int tig  = lane & 3;
    const int warp_m = (wid >> 2) * 64;
    const int warp_n = (wid & 3) * 32;
    const int block_row = blockIdx.x * BM;
    const uint32_t sbase = smem_u32p(smem);

    auto load_chunk = [&](int kc, int stage) {   // kc in 0..7
        const uint32_t aB = sbase + stage * (STG2_U32 * 4);
        const uint32_t bB = aB + B2_OFF * 4;
        const __nv_bfloat16* M = (kc < 4) ? g_n1b : g_n2b;
        const int colb = (kc & 3) * BK;
        #pragma unroll
        for (int i = 0; i < 2; i++) {
            int u  = tid + i * 256;
            int r  = u >> 2;
            int c4 = u & 3;
            int gr = block_row + r;
            if (gr >= NNODES) gr = NNODES - 1;
            cp_async16(aB + r * (A2STR * 4) + c4 * 16,
                       M + (size_t)gr * DIM + colb + c4 * 8);
        }
        const int kp0 = kc * 16;                 // u32 offset in g_Wb row
        #pragma unroll
        for (int i = 0; i < 2; i++) {
            int u  = tid + i * 256;
            int r  = u >> 2;                     // n = 0..127
            int c4 = u & 3;
            cp_async16(bB + r * (B2STR * 4) + c4 * 16,
                       reinterpret_cast<const uint32_t*>(g_Wb) +
                           (size_t)r * 128 + kp0 + c4 * 4);
        }
    };

    float acc[4][4][4];
    #pragma unroll
    for (int mt = 0; mt < 4; mt++)
        #pragma unroll
        for (int nt = 0; nt < 4; nt++)
            #pragma unroll
            for (int i = 0; i < 4; i++)
                acc[mt][nt][i] = 0.f;

    load_chunk(0, 0); CP_COMMIT();
    load_chunk(1, 1); CP_COMMIT();

    #pragma unroll 1
    for (int kc = 0; kc < 8; kc++) {
        CP_WAIT1();
        __syncthreads();
        if (kc + 2 < 8) load_chunk(kc + 2, (kc + 2) % NSTAGE);
        CP_COMMIT();

        const uint32_t* sA = smem + (kc % NSTAGE) * STG2_U32;
        const uint32_t* sB = sA + B2_OFF;
        #pragma unroll
        for (int ks = 0; ks < 2; ks++) {
            const int j = ks * 8;
            uint32_t af[4][4];
            #pragma unroll
            for (int mt = 0; mt < 4; mt++) {
                int row = warp_m + mt * 16 + gid;
                af[mt][0] = sA[row * A2STR + j + tig];
                af[mt][1] = sA[(row + 8) * A2STR + j + tig];
                af[mt][2] = sA[row * A2STR + j + tig + 4];
                af[mt][3] = sA[(row + 8) * A2STR + j + tig + 4];
            }
            uint32_t bf[4][2];
            #pragma unroll
            for (int nt = 0; nt < 4; nt++) {
                int col = warp_n + nt * 8 + gid;
                bf[nt][0] = sB[col * B2STR + j + tig];
                bf[nt][1] = sB[col * B2STR + j + tig + 4];
            }
            #pragma unroll
            for (int mt = 0; mt < 4; mt++)
                #pragma unroll
                for (int nt = 0; nt < 4; nt++)
                    mma_bf16(acc[mt][nt], af[mt], bf[nt]);
        }
        __syncthreads();
    }

    // epilogue: add fp32 partial, tanh, store
    #pragma unroll
    for (int mt = 0; mt < 4; mt++) {
        #pragma unroll
        for (int half = 0; half < 2; half++) {
            int gr = block_row + warp_m + mt * 16 + gid + half * 8;
            if (gr < NNODES) {
                #pragma unroll
                for (int nt = 0; nt < 4; nt++) {
                    const size_t off = (size_t)gr * DOUT + warp_n + nt * 8 + tig * 2;
                    float2 p = __ldg(reinterpret_cast<const float2*>(g_part + off));
                    float2 v;
                    v.x = tanhf(acc[mt][nt][half * 2 + 0] + p.x);
                    v.y = tanhf(acc[mt][nt][half * 2 + 1] + p.y);
                    *reinterpret_cast<float2*>(out + off) = v;
                }
            }
        }
    }
}

// ---------------------------------------------------------------------------
extern "C" void kernel_launch(void* const* d_in, const int* in_sizes, int n_in,
                              void* d_out, int out_size) {
    const float* node_fea1 = (const float*)d_in[0];
    const float* node_fea2 = (const float*)d_in[1];
    const int*   neigh1    = (const int*)  d_in[2];
    const int*   neigh2    = (const int*)  d_in[3];
    const float* weight    = (const float*)d_in[4];
    float*       out       = (float*)d_out;

    static cudaStream_t s2 = nullptr;
    static cudaEvent_t ev_fork = nullptr, ev_join = nullptr;
    static bool init_done = false;
    if (!init_done) {
        cudaStreamCreateWithFlags(&s2, cudaStreamNonBlocking);
        cudaEventCreateWithFlags(&ev_fork, cudaEventDisableTiming);
        cudaEventCreateWithFlags(&ev_join, cudaEventDisableTiming);
        cudaFuncSetAttribute(gemm1_kernel,
                             cudaFuncAttributeMaxDynamicSharedMemorySize,
                             NSTAGE * STG1_U32 * 4);
        cudaFuncSetAttribute(gemm2_kernel,
                             cudaFuncAttributeMaxDynamicSharedMemorySize,
                             NSTAGE * STG2_U32 * 4);
        init_done = true;
    }

    const int nblk = (NNODES + BM - 1) / BM;   // 391

    // conv on the main (capture) stream
    conv_kernel<<<(NNODES * DIM / 8 + 255) / 256, 256>>>(node_fea1, weight);

    // fork: gemm1 on s2 (independent of agg), agg stays on main stream
    cudaEventRecord(ev_fork, 0);
    cudaStreamWaitEvent(s2, ev_fork, 0);
    gemm1_kernel<<<nblk, 256, NSTAGE * STG1_U32 * 4, s2>>>(node_fea1, node_fea2);
    cudaEventRecord(ev_join, s2);

    agg_kernel<<<NNODES / 8, 256>>>(neigh1, neigh2);

    // join: gemm2 needs both agg (means) and gemm1 (partials)
    cudaStreamWaitEvent(0, ev_join, 0);
    gemm2_kernel<<<nblk, 256, NSTAGE * STG2_U32 * 4>>>(out);
}

// round 11
// speedup vs baseline: 1.0775x; 1.0775x over previous
#include <cuda_runtime.h>
#include <cuda_bf16.h>
#include <math.h>
#include <stdint.h>

#define NNODES 50000
#define KNEI   32
#define DIM    128
#define DOUT   128
#define BM     128
#define BK     32

// smem geometry (u32 units). Both halves share one stage layout:
//   A region: 4608 u32 (f-half: 128x36 fp32 | mean-half: 128x36 (64 bf16 + pad))
//   B region: starts at +4608 (f-half: 32x136 tf32 | mean-half: 128x36 bf16)
#define A1STR  36
#define B1STR  136
#define A2STR  36                     // 64 bf16 = 32 u32 + 4 pad
#define B2STR  36
#define B_OFF  4608
#define STG_U32 9216                  // max(4608+4352, 4608+4608)
#define NSTAGE 3
#define NUNIT  12                     // 8 f-chunks (K=32) + 4 mean-chunks (K=64)

// Static device scratch (allowed).
__device__ __nv_bfloat16 g_f1b[(size_t)NNODES * DIM];   // bf16(fea1)
__device__ __nv_bfloat16 g_n1b[(size_t)NNODES * DIM];   // bf16(mean nei1)
__device__ __nv_bfloat16 g_n2b[(size_t)NNODES * DIM];   // bf16(mean nei2)
__device__ uint32_t g_Wt[(size_t)256 * DOUT];           // tf32(W[0:256]), [k][n]
__device__ __nv_bfloat16 g_Wb[(size_t)DOUT * 256];      // bf16(W[256:512]), [n][k']

__device__ __forceinline__ uint32_t f2tf32(float f) {
    uint32_t u;
    asm("cvt.rna.tf32.f32 %0, %1;" : "=r"(u) : "f"(f));
    return u;
}
__device__ __forceinline__ uint32_t smem_u32p(const void* p) {
    uint32_t a;
    asm("{ .reg .u64 t; cvta.to.shared.u64 t, %1; cvt.u32.u64 %0, t; }" : "=r"(a) : "l"(p));
    return a;
}
__device__ __forceinline__ void cp_async16(uint32_t dst, const void* src) {
    asm volatile("cp.async.cg.shared.global [%0], [%1], 16;"
                 :: "r"(dst), "l"(src) : "memory");
}
#define CP_COMMIT() asm volatile("cp.async.commit_group;" ::: "memory")
#define CP_WAIT1()  asm volatile("cp.async.wait_group 1;"  ::: "memory")

__device__ __forceinline__ void mma_tf32(float c[4], const uint32_t a[4],
                                         const uint32_t b[2]) {
    asm volatile(
        "mma.sync.aligned.m16n8k8.row.col.f32.tf32.tf32.f32 "
        "{%0,%1,%2,%3}, {%4,%5,%6,%7}, {%8,%9}, {%0,%1,%2,%3};"
        : "+f"(c[0]), "+f"(c[1]), "+f"(c[2]), "+f"(c[3])
        : "r"(a[0]), "r"(a[1]), "r"(a[2]), "r"(a[3]), "r"(b[0]), "r"(b[1]));
}
__device__ __forceinline__ void mma_bf16(float c[4], const uint32_t a[4],
                                         const uint32_t b[2]) {
    asm volatile(
        "mma.sync.aligned.m16n8k16.row.col.f32.bf16.bf16.f32 "
        "{%0,%1,%2,%3}, {%4,%5,%6,%7}, {%8,%9}, {%0,%1,%2,%3};"
        : "+f"(c[0]), "+f"(c[1]), "+f"(c[2]), "+f"(c[3])
        : "r"(a[0]), "r"(a[1]), "r"(a[2]), "r"(a[3]), "r"(b[0]), "r"(b[1]));
}

// ---------------------------------------------------------------------------
// conv: fea1 -> bf16 (2 indep float4-pairs/thread) ; W[0:256] -> tf32 [k][n] ;
// W[256:512] -> bf16 [n][k']
// ---------------------------------------------------------------------------
__global__ __launch_bounds__(256)
void conv_kernel(const float* __restrict__ fea1, const float* __restrict__ W) {
    const int t = blockIdx.x * 256 + threadIdx.x;   // 0..400127
    if (t < 400000) {
        #pragma unroll
        for (int h = 0; h < 2; h++) {
            size_t p = (size_t)t + (size_t)h * 400000;   // float4-pair 0..799999
            float4 a = reinterpret_cast<const float4*>(fea1)[2 * p];
            float4 b = reinterpret_cast<const float4*>(fea1)[2 * p + 1];
            __nv_bfloat162 p0 = __floats2bfloat162_rn(a.x, a.y);
            __nv_bfloat162 p1 = __floats2bfloat162_rn(a.z, a.w);
            __nv_bfloat162 p2 = __floats2bfloat162_rn(b.x, b.y);
            __nv_bfloat162 p3 = __floats2bfloat162_rn(b.z, b.w);
            uint4 o;
            o.x = *reinterpret_cast<uint32_t*>(&p0);
            o.y = *reinterpret_cast<uint32_t*>(&p1);
            o.z = *reinterpret_cast<uint32_t*>(&p2);
            o.w = *reinterpret_cast<uint32_t*>(&p3);
            reinterpret_cast<uint4*>(g_f1b)[p] = o;
        }
    }
    if (t < (256 * DOUT) / 4) {
        float4 w = reinterpret_cast<const float4*>(W)[t];
        uint4 o;
        o.x = f2tf32(w.x); o.y = f2tf32(w.y); o.z = f2tf32(w.z); o.w = f2tf32(w.w);
        reinterpret_cast<uint4*>(g_Wt)[t] = o;
    }
    if (t < DOUT * 128) {
        int n  = t >> 7;
        int kp = t & 127;
        float w0 = W[(size_t)(256 + 2 * kp) * DOUT + n];
        float w1 = W[(size_t)(257 + 2 * kp) * DOUT + n];
        __nv_bfloat162 p = __floats2bfloat162_rn(w0, w1);
        reinterpret_cast<uint32_t*>(g_Wb)[n * 128 + kp] =
            *reinterpret_cast<uint32_t*>(&p);
    }
}

// ---------------------------------------------------------------------------
// agg: one warp per node; bf16 gather, fp32 accum, bf16 means.
// ---------------------------------------------------------------------------
__global__ __launch_bounds__(256)
void agg_kernel(const int* __restrict__ idx1, const int* __restrict__ idx2) {
    const int node = blockIdx.x * 8 + (threadIdx.x >> 5);
    const int lane = threadIdx.x & 31;
    const uint2* fb = reinterpret_cast<const uint2*>(g_f1b);
    const float sc = 1.0f / (float)KNEI;

    #pragma unroll
    for (int list = 0; list < 2; list++) {
        const int* idx = list ? idx2 : idx1;
        __nv_bfloat16* dst = list ? g_n2b : g_n1b;
        int myidx = idx[node * KNEI + lane];
        float4 a0 = make_float4(0.f, 0.f, 0.f, 0.f);
        float4 a1 = make_float4(0.f, 0.f, 0.f, 0.f);
        #pragma unroll
        for (int j = 0; j < KNEI; j += 2) {
            int i0 = __shfl_sync(0xffffffffu, myidx, j + 0);
            int i1 = __shfl_sync(0xffffffffu, myidx, j + 1);
            uint2 v0 = __ldg(&fb[(size_t)i0 * 32 + lane]);
            uint2 v1 = __ldg(&fb[(size_t)i1 * 32 + lane]);
            float2 l0 = __bfloat1622float2(*reinterpret_cast<__nv_bfloat162*>(&v0.x));
            float2 h0 = __bfloat1622float2(*reinterpret_cast<__nv_bfloat162*>(&v0.y));
            float2 l1 = __bfloat1622float2(*reinterpret_cast<__nv_bfloat162*>(&v1.x));
            float2 h1 = __bfloat1622float2(*reinterpret_cast<__nv_bfloat162*>(&v1.y));
            a0.x += l0.x; a0.y += l0.y; a0.z += h0.x; a0.w += h0.y;
            a1.x += l1.x; a1.y += l1.y; a1.z += h1.x; a1.w += h1.y;
        }
        __nv_bfloat162 m0 = __floats2bfloat162_rn((a0.x + a1.x) * sc, (a0.y + a1.y) * sc);
        __nv_bfloat162 m1 = __floats2bfloat162_rn((a0.z + a1.z) * sc, (a0.w + a1.w) * sc);
        uint2 o;
        o.x = *reinterpret_cast<uint32_t*>(&m0);
        o.y = *reinterpret_cast<uint32_t*>(&m1);
        *reinterpret_cast<uint2*>(&dst[(size_t)node * DIM + lane * 4]) = o;
    }
}

// ---------------------------------------------------------------------------
// gemm: out = tanh([f1|f2|n1|n2] @ W), 3-stage cp.async pipeline, 12 units:
//   units 0..7 : fp32 A (reg tf32 cvt) x tf32 B[k][n], K=32, m16n8k8
//   units 8..11: bf16 A (means) x bf16 B[n][k'], K=64, 4 x m16n8k16
// ---------------------------------------------------------------------------
__global__ __launch_bounds__(256, 2)
void gemm_kernel(const float* __restrict__ fea1,
                 const float* __restrict__ fea2,
                 float* __restrict__ out) {
    extern __shared__ uint32_t smem[];

    const int tid  = threadIdx.x;
    const int wid  = tid >> 5;
    const int lane = tid & 31;
    const int gid  = lane >> 2;
    const int tig  = lane & 3;
    const int warp_m = (wid >> 2) * 64;
    const int warp_n = (wid & 3) * 32;
    const int block_row = blockIdx.x * BM;
    const uint32_t sbase = smem_u32p(smem);

    auto load_unit = [&](int p, int stage) {
        const uint32_t aB = sbase + stage * (STG_U32 * 4);
        const uint32_t bB = aB + B_OFF * 4;
        if (p < 8) {
            const float* F = (p < 4) ? fea1 : fea2;
            const int colb = (p & 3) * BK;
            #pragma unroll
            for (int i = 0; i < 4; i++) {
                int u  = tid + i * 256;
                int r  = u >> 3;
                int c4 = u & 7;
                int gr = block_row + r;
                if (gr >= NNODES) gr = NNODES - 1;
                cp_async16(aB + r * (A1STR * 4) + c4 * 16,
                           F + (size_t)gr * DIM + colb + c4 * 4);
            }
            #pragma unroll
            for (int i = 0; i < 4; i++) {
                int u  = tid + i * 256;
                int k  = u >> 5;
                int n4 = u & 31;
                cp_async16(bB + k * (B1STR * 4) + n4 * 16,
                           g_Wt + (size_t)(p * BK + k) * DOUT + n4 * 4);
            }
        } else {
            const int kc2 = p - 8;                     // 0..3
            const __nv_bfloat16* M = (kc2 < 2) ? g_n1b : g_n2b;
            const int colb = (kc2 & 1) * 64;           // bf16 col offset
            #pragma unroll
            for (int i = 0; i < 4; i++) {
                int u  = tid + i * 256;                // 0..1023
                int r  = u >> 3;                       // 0..127
                int c4 = u & 7;                        // 0..7 (16B = 8 bf16)
                int gr = block_row + r;
                if (gr >= NNODES) gr = NNODES - 1;
                cp_async16(aB + r * (A2STR * 4) + c4 * 16,
                           M + (size_t)gr * DIM + colb + c4 * 8);
            }
            const int kp0 = kc2 * 32;                  // u32 offset in g_Wb row
            #pragma unroll
            for (int i = 0; i < 4; i++) {
                int u  = tid + i * 256;
                int r  = u >> 3;                       // n = 0..127
                int c4 = u & 7;
                cp_async16(bB + r * (B2STR * 4) + c4 * 16,
                           reinterpret_cast<const uint32_t*>(g_Wb) +
                               (size_t)r * 128 + kp0 + c4 * 4);
            }
        }
    };

    float acc[4][4][4];
    #pragma unroll
    for (int mt = 0; mt < 4; mt++)
        #pragma unroll
        for (int nt = 0; nt < 4; nt++)
            #pragma unroll
            for (int i = 0; i < 4; i++)
                acc[mt][nt][i] = 0.f;

    load_unit(0, 0); CP_COMMIT();
    load_unit(1, 1); CP_COMMIT();

    #pragma unroll 1
    for (int p = 0; p < NUNIT; p++) {
        CP_WAIT1();
        __syncthreads();
        if (p + 2 < NUNIT) load_unit(p + 2, (p + 2) % NSTAGE);
        CP_COMMIT();

        const uint32_t* sA = smem + (p % NSTAGE) * STG_U32;
        const uint32_t* sB = sA + B_OFF;

        if (p < 8) {
            #pragma unroll
            for (int ks = 0; ks < 4; ks++) {
                const int ko = ks * 8;
                uint32_t af[4][4];
                #pragma unroll
                for (int mt = 0; mt < 4; mt++) {
                    int row = warp_m + mt * 16 + gid;
                    af[mt][0] = f2tf32(__uint_as_float(sA[row * A1STR + ko + tig]));
                    af[mt][1] = f2tf32(__uint_as_float(sA[(row + 8) * A1STR + ko + tig]));
                    af[mt][2] = f2tf32(__uint_as_float(sA[row * A1STR + ko + tig + 4]));
                    af[mt][3] = f2tf32(__uint_as_float(sA[(row + 8) * A1STR + ko + tig + 4]));
                }
                uint32_t bf[4][2];
                #pragma unroll
                for (int nt = 0; nt < 4; nt++) {
                    int col = warp_n + nt * 8 + gid;
                    bf[nt][0] = sB[(ko + tig) * B1STR + col];
                    bf[nt][1] = sB[(ko + tig + 4) * B1STR + col];
                }
                #pragma unroll
                for (int mt = 0; mt < 4; mt++)
                    #pragma unroll
                    for (int nt = 0; nt < 4; nt++)
                        mma_tf32(acc[mt][nt], af[mt], bf[nt]);
            }
        } else {
            #pragma unroll
            for (int ks = 0; ks < 4; ks++) {           // 4 x k16 (K=64)
                const int j = ks * 8;                  // u32 offset (16 bf16)
                uint32_t af[4][4];
                #pragma unroll
                for (int mt = 0; mt < 4; mt++) {
                    int row = warp_m + mt * 16 + gid;
                    af[mt][0] = sA[row * A2STR + j + tig];
                    af[mt][1] = sA[(row + 8) * A2STR + j + tig];
                    af[mt][2] = sA[row * A2STR + j + tig + 4];
                    af[mt][3] = sA[(row + 8) * A2STR + j + tig + 4];
                }
                uint32_t bf[4][2];
                #pragma unroll
                for (int nt = 0; nt < 4; nt++) {
                    int col = warp_n + nt * 8 + gid;
                    bf[nt][0] = sB[col * B2STR + j + tig];
                    bf[nt][1] = sB[col * B2STR + j + tig + 4];
                }
                #pragma unroll
                for (int mt = 0; mt < 4; mt++)
                    #pragma unroll
                    for (int nt = 0; nt < 4; nt++)
                        mma_bf16(acc[mt][nt], af[mt], bf[nt]);
            }
        }
        __syncthreads();
    }

    // epilogue: tanh + store
    #pragma unroll
    for (int mt = 0; mt < 4; mt++) {
        #pragma unroll
        for (int half = 0; half < 2; half++) {
            int gr = block_row + warp_m + mt * 16 + gid + half * 8;
            if (gr < NNODES) {
                #pragma unroll
                for (int nt = 0; nt < 4; nt++) {
                    float2 v;
                    v.x = tanhf(acc[mt][nt][half * 2 + 0]);
                    v.y = tanhf(acc[mt][nt][half * 2 + 1]);
                    *reinterpret_cast<float2*>(
                        out + (size_t)gr * DOUT + warp_n + nt * 8 + tig * 2) = v;
                }
            }
        }
    }
}

// ---------------------------------------------------------------------------
extern "C" void kernel_launch(void* const* d_in, const int* in_sizes, int n_in,
                              void* d_out, int out_size) {
    const float* node_fea1 = (const float*)d_in[0];
    const float* node_fea2 = (const float*)d_in[1];
    const int*   neigh1    = (const int*)  d_in[2];
    const int*   neigh2    = (const int*)  d_in[3];
    const float* weight    = (const float*)d_in[4];
    float*       out       = (float*)d_out;

    const int dyn_smem = NSTAGE * STG_U32 * 4;   // 110592 B
    static bool attr_set = false;
    if (!attr_set) {
        cudaFuncSetAttribute(gemm_kernel,
                             cudaFuncAttributeMaxDynamicSharedMemorySize, dyn_smem);
        attr_set = true;
    }

    conv_kernel<<<(400000 + 255) / 256, 256>>>(node_fea1, weight);
    agg_kernel<<<NNODES / 8, 256>>>(neigh1, neigh2);
    gemm_kernel<<<(NNODES + BM - 1) / BM, 256, dyn_smem>>>(node_fea1, node_fea2, out);
}

// round 12
// speedup vs baseline: 1.2600x; 1.1694x over previous
#include <cuda_runtime.h>
#include <cuda_fp16.h>
#include <math.h>
#include <stdint.h>

#define NNODES 50000
#define KNEI   32
#define DIM    128
#define DOUT   128
#define BM     128

// gemm smem geometry (u32): A 128x36 (64 fp16 + pad), B 128x36
#define ASTR   36
#define B_OFF  (BM * ASTR)            // 4608
#define STG_U32 (2 * BM * ASTR)       // 9216
#define NSTAGE 3
#define NUNIT  8                      // 8 units x K=64 = 512

// Static device scratch (allowed).
__device__ __half g_f1h[(size_t)NNODES * DIM];   // fp16(fea1)
__device__ __half g_f2h[(size_t)NNODES * DIM];   // fp16(fea2)
__device__ __half g_n1h[(size_t)NNODES * DIM];   // fp16(mean nei1)
__device__ __half g_n2h[(size_t)NNODES * DIM];   // fp16(mean nei2)
__device__ __half g_Wh [(size_t)DOUT * 512];     // fp16(W), [n][k]

__device__ __forceinline__ uint32_t smem_u32p(const void* p) {
    uint32_t a;
    asm("{ .reg .u64 t; cvta.to.shared.u64 t, %1; cvt.u32.u64 %0, t; }" : "=r"(a) : "l"(p));
    return a;
}
__device__ __forceinline__ void cp_async16(uint32_t dst, const void* src) {
    asm volatile("cp.async.cg.shared.global [%0], [%1], 16;"
                 :: "r"(dst), "l"(src) : "memory");
}
#define CP_COMMIT() asm volatile("cp.async.commit_group;" ::: "memory")
#define CP_WAIT1()  asm volatile("cp.async.wait_group 1;"  ::: "memory")

__device__ __forceinline__ void mma_f16(float c[4], const uint32_t a[4],
                                        const uint32_t b[2]) {
    asm volatile(
        "mma.sync.aligned.m16n8k16.row.col.f32.f16.f16.f32 "
        "{%0,%1,%2,%3}, {%4,%5,%6,%7}, {%8,%9}, {%0,%1,%2,%3};"
        : "+f"(c[0]), "+f"(c[1]), "+f"(c[2]), "+f"(c[3])
        : "r"(a[0]), "r"(a[1]), "r"(a[2]), "r"(a[3]), "r"(b[0]), "r"(b[1]));
}

// ---------------------------------------------------------------------------
// conv: fea1 -> fp16 (16 floats/thread) ; W -> fp16 [n][k] (transposed)
// ---------------------------------------------------------------------------
__global__ __launch_bounds__(256)
void conv_kernel(const float* __restrict__ fea1, const float* __restrict__ W) {
    const int t = blockIdx.x * 256 + threadIdx.x;   // 0..400127
    if (t < 400000) {
        #pragma unroll
        for (int h = 0; h < 2; h++) {
            size_t p = (size_t)t + (size_t)h * 400000;   // float4-pair idx
            float4 a = reinterpret_cast<const float4*>(fea1)[2 * p];
            float4 b = reinterpret_cast<const float4*>(fea1)[2 * p + 1];
            __half2 p0 = __floats2half2_rn(a.x, a.y);
            __half2 p1 = __floats2half2_rn(a.z, a.w);
            __half2 p2 = __floats2half2_rn(b.x, b.y);
            __half2 p3 = __floats2half2_rn(b.z, b.w);
            uint4 o;
            o.x = *reinterpret_cast<uint32_t*>(&p0);
            o.y = *reinterpret_cast<uint32_t*>(&p1);
            o.z = *reinterpret_cast<uint32_t*>(&p2);
            o.w = *reinterpret_cast<uint32_t*>(&p3);
            reinterpret_cast<uint4*>(g_f1h)[p] = o;
        }
    }
    if (t < DOUT * 256) {          // W transpose: 32768 threads, 2 k's each
        int n  = t >> 8;           // 0..127
        int kp = t & 255;          // u32 idx: k = 2kp, 2kp+1
        float w0 = W[(size_t)(2 * kp) * DOUT + n];
        float w1 = W[(size_t)(2 * kp + 1) * DOUT + n];
        __half2 p = __floats2half2_rn(w0, w1);
        reinterpret_cast<uint32_t*>(g_Wh)[n * 256 + kp] =
            *reinterpret_cast<uint32_t*>(&p);
    }
}

// ---------------------------------------------------------------------------
// agg: (a) convert a fea2 slice to fp16 (DRAM work rides under L2-bound gather)
//      (b) one warp per node: fp16 gather, fp32 accum, fp16 means.
// ---------------------------------------------------------------------------
__global__ __launch_bounds__(256)
void agg_kernel(const float* __restrict__ fea2,
                const int* __restrict__ idx1, const int* __restrict__ idx2) {
    const int tid  = threadIdx.x;
    const int lane = tid & 31;

    // fea2 fp16 conversion: 6250 blocks x 256 thr x 4 floats = 6.4M exact
    {
        size_t p = (size_t)blockIdx.x * 256 + tid;   // float4 index
        float4 a = reinterpret_cast<const float4*>(fea2)[p];
        __half2 p0 = __floats2half2_rn(a.x, a.y);
        __half2 p1 = __floats2half2_rn(a.z, a.w);
        uint2 o;
        o.x = *reinterpret_cast<uint32_t*>(&p0);
        o.y = *reinterpret_cast<uint32_t*>(&p1);
        reinterpret_cast<uint2*>(g_f2h)[p] = o;
    }

    const int node = blockIdx.x * 8 + (tid >> 5);
    const uint2* fh = reinterpret_cast<const uint2*>(g_f1h);
    const float sc = 1.0f / (float)KNEI;

    #pragma unroll
    for (int list = 0; list < 2; list++) {
        const int* idx = list ? idx2 : idx1;
        __half* dst = list ? g_n2h : g_n1h;
        int myidx = idx[node * KNEI + lane];
        float4 a0 = make_float4(0.f, 0.f, 0.f, 0.f);
        float4 a1 = make_float4(0.f, 0.f, 0.f, 0.f);
        #pragma unroll
        for (int j = 0; j < KNEI; j += 2) {
            int i0 = __shfl_sync(0xffffffffu, myidx, j + 0);
            int i1 = __shfl_sync(0xffffffffu, myidx, j + 1);
            uint2 v0 = __ldg(&fh[(size_t)i0 * 32 + lane]);
            uint2 v1 = __ldg(&fh[(size_t)i1 * 32 + lane]);
            float2 l0 = __half22float2(*reinterpret_cast<__half2*>(&v0.x));
            float2 h0 = __half22float2(*reinterpret_cast<__half2*>(&v0.y));
            float2 l1 = __half22float2(*reinterpret_cast<__half2*>(&v1.x));
            float2 h1 = __half22float2(*reinterpret_cast<__half2*>(&v1.y));
            a0.x += l0.x; a0.y += l0.y; a0.z += h0.x; a0.w += h0.y;
            a1.x += l1.x; a1.y += l1.y; a1.z += h1.x; a1.w += h1.y;
        }
        __half2 m0 = __floats2half2_rn((a0.x + a1.x) * sc, (a0.y + a1.y) * sc);
        __half2 m1 = __floats2half2_rn((a0.z + a1.z) * sc, (a0.w + a1.w) * sc);
        uint2 o;
        o.x = *reinterpret_cast<uint32_t*>(&m0);
        o.y = *reinterpret_cast<uint32_t*>(&m1);
        *reinterpret_cast<uint2*>(&dst[(size_t)node * DIM + lane * 4]) = o;
    }
}

// ---------------------------------------------------------------------------
// gemm: out = tanh([f1|f2|n1|n2] @ W), all fp16 m16n8k16, 8 units x K=64,
// 3-stage cp.async pipeline.
// ---------------------------------------------------------------------------
__global__ __launch_bounds__(256, 2)
void gemm_kernel(float* __restrict__ out) {
    extern __shared__ uint32_t smem[];

    const int tid  = threadIdx.x;
    const int wid  = tid >> 5;
    const int lane = tid & 31;
    const int gid  = lane >> 2;
    const int tig  = lane & 3;
    const int warp_m = (wid >> 2) * 64;
    const int warp_n = (wid & 3) * 32;
    const int block_row = blockIdx.x * BM;
    const uint32_t sbase = smem_u32p(smem);

    auto load_unit = [&](int p, int stage) {
        const uint32_t aB = sbase + stage * (STG_U32 * 4);
        const uint32_t bB = aB + B_OFF * 4;
        const __half* srcs[4] = {g_f1h, g_f2h, g_n1h, g_n2h};
        const __half* A = srcs[p >> 1];
        const int colb = (p & 1) * 64;
        #pragma unroll
        for (int i = 0; i < 4; i++) {
            int u  = tid + i * 256;            // 0..1023
            int r  = u >> 3;                   // 0..127
            int c4 = u & 7;                    // 0..7 (16B = 8 fp16)
            int gr = block_row + r;
            if (gr >= NNODES) gr = NNODES - 1;
            cp_async16(aB + r * (ASTR * 4) + c4 * 16,
                       A + (size_t)gr * DIM + colb + c4 * 8);
        }
        const int kp0 = p * 32;                // u32 offset into g_Wh row
        #pragma unroll
        for (int i = 0; i < 4; i++) {
            int u  = tid + i * 256;
            int r  = u >> 3;                   // n = 0..127
            int c4 = u & 7;
            cp_async16(bB + r * (ASTR * 4) + c4 * 16,
                       reinterpret_cast<const uint32_t*>(g_Wh) +
                           (size_t)r * 256 + kp0 + c4 * 4);
        }
    };

    float acc[4][4][4];
    #pragma unroll
    for (int mt = 0; mt < 4; mt++)
        #pragma unroll
        for (int nt = 0; nt < 4; nt++)
            #pragma unroll
            for (int i = 0; i < 4; i++)
                acc[mt][nt][i] = 0.f;

    load_unit(0, 0); CP_COMMIT();
    load_unit(1, 1); CP_COMMIT();

    #pragma unroll 1
    for (int p = 0; p < NUNIT; p++) {
        CP_WAIT1();
        __syncthreads();
        if (p + 2 < NUNIT) load_unit(p + 2, (p + 2) % NSTAGE);
        CP_COMMIT();

        const uint32_t* sA = smem + (p % NSTAGE) * STG_U32;
        const uint32_t* sB = sA + B_OFF;

        #pragma unroll
        for (int ks = 0; ks < 4; ks++) {       // 4 x k16 = K64
            const int j = ks * 8;              // u32 offset (16 fp16)
            uint32_t af[4][4];
            #pragma unroll
            for (int mt = 0; mt < 4; mt++) {
                int row = warp_m + mt * 16 + gid;
                af[mt][0] = sA[row * ASTR + j + tig];
                af[mt][1] = sA[(row + 8) * ASTR + j + tig];
                af[mt][2] = sA[row * ASTR + j + tig + 4];
                af[mt][3] = sA[(row + 8) * ASTR + j + tig + 4];
            }
            uint32_t bf[4][2];
            #pragma unroll
            for (int nt = 0; nt < 4; nt++) {
                int col = warp_n + nt * 8 + gid;
                bf[nt][0] = sB[col * ASTR + j + tig];
                bf[nt][1] = sB[col * ASTR + j + tig + 4];
            }
            #pragma unroll
            for (int mt = 0; mt < 4; mt++)
                #pragma unroll
                for (int nt = 0; nt < 4; nt++)
                    mma_f16(acc[mt][nt], af[mt], bf[nt]);
        }
        __syncthreads();
    }

    // epilogue: tanh + store
    #pragma unroll
    for (int mt = 0; mt < 4; mt++) {
        #pragma unroll
        for (int half = 0; half < 2; half++) {
            int gr = block_row + warp_m + mt * 16 + gid + half * 8;
            if (gr < NNODES) {
                #pragma unroll
                for (int nt = 0; nt < 4; nt++) {
                    float2 v;
                    v.x = tanhf(acc[mt][nt][half * 2 + 0]);
                    v.y = tanhf(acc[mt][nt][half * 2 + 1]);
                    *reinterpret_cast<float2*>(
                        out + (size_t)gr * DOUT + warp_n + nt * 8 + tig * 2) = v;
                }
            }
        }
    }
}

// ---------------------------------------------------------------------------
extern "C" void kernel_launch(void* const* d_in, const int* in_sizes, int n_in,
                              void* d_out, int out_size) {
    const float* node_fea1 = (const float*)d_in[0];
    const float* node_fea2 = (const float*)d_in[1];
    const int*   neigh1    = (const int*)  d_in[2];
    const int*   neigh2    = (const int*)  d_in[3];
    const float* weight    = (const float*)d_in[4];
    float*       out       = (float*)d_out;

    const int dyn_smem = NSTAGE * STG_U32 * 4;   // 110592 B
    static bool attr_set = false;
    if (!attr_set) {
        cudaFuncSetAttribute(gemm_kernel,
                             cudaFuncAttributeMaxDynamicSharedMemorySize, dyn_smem);
        attr_set = true;
    }

    conv_kernel<<<(400128 + 255) / 256, 256>>>(node_fea1, weight);
    agg_kernel<<<NNODES / 8, 256>>>(node_fea2, neigh1, neigh2);
    gemm_kernel<<<(NNODES + BM - 1) / BM, 256, dyn_smem>>>(out);
}